// round 5
// baseline (speedup 1.0000x reference)
#include <cuda_runtime.h>
#include <cuda_bf16.h>
#include <cstdint>

// ---------------------------------------------------------------------------
// Problem constants
// ---------------------------------------------------------------------------
#define NUM_MODALS 4
#define SHARED_IDX 3
#define CDIM       768
#define RANK       16
#define ROWS_PER_M 8192
#define TOTAL_ROWS 32768

// int8 limb storage + scales (device globals = allowed scratch)
__device__ int8_t g_Xh[TOTAL_ROWS * CDIM];
__device__ int8_t g_Xl[TOTAL_ROWS * CDIM];
__device__ int8_t g_Wh[NUM_MODALS * CDIM * CDIM];
__device__ int8_t g_Wl[NUM_MODALS * CDIM * CDIM];
__device__ float  g_sxinv[TOTAL_ROWS];
__device__ float  g_swinv[NUM_MODALS * CDIM];

// ---------------------------------------------------------------------------
// Helpers
// ---------------------------------------------------------------------------
__device__ __forceinline__ uint32_t smem_u32(const void* p) {
    uint32_t a;
    asm("{ .reg .u64 t; cvta.to.shared.u64 t, %1; cvt.u32.u64 %0, t; }"
        : "=r"(a) : "l"(p));
    return a;
}
__device__ __forceinline__ void cp_async16(uint32_t dst, const void* src) {
    asm volatile("cp.async.cg.shared.global [%0], [%1], 16;"
                 :: "r"(dst), "l"(src) : "memory");
}
__device__ __forceinline__ void cp_commit() {
    asm volatile("cp.async.commit_group;" ::: "memory");
}
template <int N>
__device__ __forceinline__ void cp_wait() {
    asm volatile("cp.async.wait_group %0;" :: "n"(N) : "memory");
}
__device__ __forceinline__ void ldm_x4(uint32_t& r0, uint32_t& r1,
                                       uint32_t& r2, uint32_t& r3,
                                       uint32_t addr) {
    asm volatile("ldmatrix.sync.aligned.m8n8.x4.shared.b16 {%0,%1,%2,%3}, [%4];"
                 : "=r"(r0), "=r"(r1), "=r"(r2), "=r"(r3) : "r"(addr));
}
__device__ __forceinline__ void imma_s8(int& d0, int& d1, int& d2, int& d3,
                                        uint32_t a0, uint32_t a1, uint32_t a2, uint32_t a3,
                                        uint32_t b0, uint32_t b1) {
    asm volatile("mma.sync.aligned.m16n8k32.row.col.s32.s8.s8.s32 "
                 "{%0,%1,%2,%3}, {%4,%5,%6,%7}, {%8,%9}, {%0,%1,%2,%3};"
                 : "+r"(d0), "+r"(d1), "+r"(d2), "+r"(d3)
                 : "r"(a0), "r"(a1), "r"(a2), "r"(a3), "r"(b0), "r"(b1));
}

// block-wide (192-thread, 6-warp) max reduction
__device__ __forceinline__ float block_max_192(float m, float* red) {
#pragma unroll
    for (int off = 16; off > 0; off >>= 1)
        m = fmaxf(m, __shfl_xor_sync(0xffffffff, m, off));
    if ((threadIdx.x & 31) == 0) red[threadIdx.x >> 5] = m;
    __syncthreads();
    float r = fmaxf(fmaxf(fmaxf(red[0], red[1]), fmaxf(red[2], red[3])),
                    fmaxf(red[4], red[5]));
    return r;
}

__device__ __forceinline__ void quant_pair(float v, float s, int8_t& h, int8_t& l) {
    float xs = v * s;
    float hf = rintf(xs);
    hf = fminf(127.f, fmaxf(-127.f, hf));
    float lf = rintf((xs - hf) * 128.f);
    h = (int8_t)(int)hf;
    l = (int8_t)(int)lf;
}

// ---------------------------------------------------------------------------
// Kernel 1: per-row quantize x into int8 limbs (192 thr/block, 1 block/row)
// ---------------------------------------------------------------------------
__global__ __launch_bounds__(192)
void quant_x_kernel(const float* __restrict__ x) {
    __shared__ float red[6];
    const int row = blockIdx.x;
    const int t = threadIdx.x;
    const float4 v = reinterpret_cast<const float4*>(x + (size_t)row * CDIM)[t];

    float m = fmaxf(fmaxf(fabsf(v.x), fabsf(v.y)), fmaxf(fabsf(v.z), fabsf(v.w)));
    float rowmax = fmaxf(block_max_192(m, red), 1e-20f);
    const float sx = 127.f / rowmax;

    int8_t h[4], l[4];
    quant_pair(v.x, sx, h[0], l[0]);
    quant_pair(v.y, sx, h[1], l[1]);
    quant_pair(v.z, sx, h[2], l[2]);
    quant_pair(v.w, sx, h[3], l[3]);
    const size_t o = (size_t)row * CDIM + t * 4;
    *reinterpret_cast<char4*>(g_Xh + o) = make_char4(h[0], h[1], h[2], h[3]);
    *reinterpret_cast<char4*>(g_Xl + o) = make_char4(l[0], l[1], l[2], l[3]);
    if (t == 0) g_sxinv[row] = rowmax * (1.f / 127.f);
}

// ---------------------------------------------------------------------------
// Kernel 2: build W_eff row (m,o), quantize into int8 limbs
// ---------------------------------------------------------------------------
__global__ __launch_bounds__(192)
void quant_w_kernel(const float* __restrict__ Wp,
                    const float* __restrict__ A,
                    const float* __restrict__ Bw) {
    __shared__ float red[6];
    const int mo = blockIdx.x;          // m*768 + o
    const int m = mo / CDIM;
    const int o = mo % CDIM;
    const int t = threadIdx.x;

    const float* A3 = A + SHARED_IDX * RANK * CDIM;
    const float* B3 = Bw + SHARED_IDX * CDIM * RANK + o * RANK;
    const float* Am = A + m * RANK * CDIM;
    const float* Bm = Bw + m * CDIM * RANK + o * RANK;

    float s[4];
    float mx = 0.f;
#pragma unroll
    for (int q = 0; q < 4; q++) {
        const int c = t * 4 + q;
        float v = Wp[o * CDIM + c];
#pragma unroll
        for (int r = 0; r < RANK; r++) {
            v += B3[r] * A3[r * CDIM + c];
            v += Bm[r] * Am[r * CDIM + c];
        }
        s[q] = v;
        mx = fmaxf(mx, fabsf(v));
    }
    float wmax = fmaxf(block_max_192(mx, red), 1e-20f);
    const float sw = 127.f / wmax;

    int8_t h[4], l[4];
#pragma unroll
    for (int q = 0; q < 4; q++) quant_pair(s[q], sw, h[q], l[q]);
    const size_t off = (size_t)mo * CDIM + t * 4;
    *reinterpret_cast<char4*>(g_Wh + off) = make_char4(h[0], h[1], h[2], h[3]);
    *reinterpret_cast<char4*>(g_Wl + off) = make_char4(l[0], l[1], l[2], l[3]);
    if (t == 0) g_swinv[mo] = wmax * (1.f / 127.f);
}

// ---------------------------------------------------------------------------
// Kernel 3: int8 limb GEMM via mma.sync.m16n8k32.s8.
// CTA tile 128x128, K-chunk 64 bytes, 8 warps (2x4), warp tile 64x32.
// acc1 = Xh*Wh ; acc2 = Xh*Wl + Xl*Wh (shared 1/128 scale).
// out = (acc1 + acc2/128) * sxinv[row] * swinv[col] + bias.
// ---------------------------------------------------------------------------
#define KC     64                 // int8 K elems per chunk (64 bytes)
#define NCHK   (CDIM / KC)        // 12
#define LDT    80                 // smem bytes per tile row (64 data + 16 pad)
#define OPB    (128 * LDT)        // 10240 bytes per operand tile
#define STB    (4 * OPB)          // 40960 per stage (Xh,Xl,Wh,Wl)
#define OFF_XH 0
#define OFF_XL OPB
#define OFF_WH (2 * OPB)
#define OFF_WL (3 * OPB)
#define STAGES 3
#define SMEM_TOTAL (STAGES * STB) // 122880

__device__ __forceinline__ void issue_chunk(const int8_t* __restrict__ xh,
                                            const int8_t* __restrict__ xl,
                                            const int8_t* __restrict__ wh,
                                            const int8_t* __restrict__ wl,
                                            int row0, int col0, int kbase,
                                            uint32_t sstage, int tid) {
#pragma unroll
    for (int i = 0; i < 2; i++) {
        int idx = i * 256 + tid;       // 0..511
        int row = idx >> 2;            // 0..127
        int ch  = idx & 3;             // 16B chunk within 64B row
        uint32_t soff = row * LDT + ch * 16;
        size_t agoff = (size_t)(row0 + row) * CDIM + kbase + ch * 16;
        size_t bgoff = (size_t)(col0 + row) * CDIM + kbase + ch * 16;
        cp_async16(sstage + OFF_XH + soff, xh + agoff);
        cp_async16(sstage + OFF_XL + soff, xl + agoff);
        cp_async16(sstage + OFF_WH + soff, wh + bgoff);
        cp_async16(sstage + OFF_WL + soff, wl + bgoff);
    }
    cp_commit();
}

__global__ __launch_bounds__(256, 1)
void lora_imma_gemm(const float* __restrict__ bp, float* __restrict__ out) {
    extern __shared__ char smem[];
    const uint32_t sbase = smem_u32(smem);
    const int tid  = threadIdx.x;
    const int wid  = tid >> 5;
    const int lane = tid & 31;
    const int warp_m = wid >> 2;       // 0..1  (64 rows each)
    const int warp_n = wid & 3;        // 0..3  (32 cols each)

    const int row0 = blockIdx.y * 128;
    const int col0 = blockIdx.x * 128;
    const int modality = row0 / ROWS_PER_M;
    const int8_t* Wh = g_Wh + (size_t)modality * CDIM * CDIM;
    const int8_t* Wl = g_Wl + (size_t)modality * CDIM * CDIM;

    int acc1[4][4][4], acc2[4][4][4];
#pragma unroll
    for (int i = 0; i < 4; i++)
#pragma unroll
        for (int j = 0; j < 4; j++)
#pragma unroll
            for (int r = 0; r < 4; r++) { acc1[i][j][r] = 0; acc2[i][j][r] = 0; }

    // ldmatrix lane addressing (byte-identical to bf16 k16 case)
    const int mat = lane >> 3;         // 8x8 tile index (0..3)
    const int mr  = lane & 7;          // row within tile
    // A frag (16 rows x 32B): T0=(m0-7,B0-15) T1=(m8-15,B0-15) T2=(m0-7,B16-31) T3=(m8-15,B16-31)
    const int a_row  = warp_m * 64 + (mat & 1) * 8 + mr;     // + i*16
    const int a_colb = (mat >> 1) * 16;                      // + kk*32
    // B frag (16 cols x 32B): T0=(n0-7,B0-15) T1=(n0-7,B16-31) T2=(n8-15,B0-15) T3=(n8-15,B16-31)
    const int b_row  = warp_n * 32 + (mat >> 1) * 8 + mr;    // + jh*16
    const int b_colb = (mat & 1) * 16;                       // + kk*32

    // Prologue: 2 chunks in flight
    issue_chunk(g_Xh, g_Xl, Wh, Wl, row0, col0, 0,  sbase + 0 * STB, tid);
    issue_chunk(g_Xh, g_Xl, Wh, Wl, row0, col0, KC, sbase + 1 * STB, tid);

    for (int c = 0; c < NCHK; c++) {
        if (c == NCHK - 1) cp_wait<0>(); else cp_wait<1>();
        __syncthreads();

        if (c + 2 < NCHK)
            issue_chunk(g_Xh, g_Xl, Wh, Wl, row0, col0, (c + 2) * KC,
                        sbase + ((c + 2) % STAGES) * STB, tid);

        const uint32_t st = sbase + (c % STAGES) * STB;
        const uint32_t sXH = st + OFF_XH, sXL = st + OFF_XL;
        const uint32_t sWH = st + OFF_WH, sWL = st + OFF_WL;

#pragma unroll
        for (int kk = 0; kk < 2; kk++) {      // two k32 slabs per 64B chunk
            uint32_t bh[4][2], bl[4][2];
#pragma unroll
            for (int jh = 0; jh < 2; jh++) {
                uint32_t boff = (uint32_t)(b_row + jh * 16) * LDT + kk * 32 + b_colb;
                uint32_t r0, r1, r2, r3;
                ldm_x4(r0, r1, r2, r3, sWH + boff);
                bh[2 * jh][0] = r0; bh[2 * jh][1] = r1;
                bh[2 * jh + 1][0] = r2; bh[2 * jh + 1][1] = r3;
                ldm_x4(r0, r1, r2, r3, sWL + boff);
                bl[2 * jh][0] = r0; bl[2 * jh][1] = r1;
                bl[2 * jh + 1][0] = r2; bl[2 * jh + 1][1] = r3;
            }
#pragma unroll
            for (int i = 0; i < 4; i++) {
                uint32_t aoff = (uint32_t)(a_row + i * 16) * LDT + kk * 32 + a_colb;
                uint32_t ah0, ah1, ah2, ah3, al0, al1, al2, al3;
                ldm_x4(ah0, ah1, ah2, ah3, sXH + aoff);
                ldm_x4(al0, al1, al2, al3, sXL + aoff);
                // Spread dependency chains: acc2[i][j] touched in two separate j-sweeps
#pragma unroll
                for (int j = 0; j < 4; j++)
                    imma_s8(acc1[i][j][0], acc1[i][j][1], acc1[i][j][2], acc1[i][j][3],
                            ah0, ah1, ah2, ah3, bh[j][0], bh[j][1]);
#pragma unroll
                for (int j = 0; j < 4; j++)
                    imma_s8(acc2[i][j][0], acc2[i][j][1], acc2[i][j][2], acc2[i][j][3],
                            ah0, ah1, ah2, ah3, bl[j][0], bl[j][1]);
#pragma unroll
                for (int j = 0; j < 4; j++)
                    imma_s8(acc2[i][j][0], acc2[i][j][1], acc2[i][j][2], acc2[i][j][3],
                            al0, al1, al2, al3, bh[j][0], bh[j][1]);
            }
        }
    }

    // Epilogue: dequant + bias. C frag: lane t -> rows (t/4, t/4+8), cols (t%4)*2..+1
    const int gID = lane >> 2;
    const int tg  = lane & 3;
    const float* swinv = g_swinv + modality * CDIM;
#pragma unroll
    for (int j = 0; j < 4; j++) {
        const int col = col0 + warp_n * 32 + j * 8 + tg * 2;
        const float2 bb = *reinterpret_cast<const float2*>(bp + col);
        const float sw0 = swinv[col], sw1 = swinv[col + 1];
#pragma unroll
        for (int i = 0; i < 4; i++) {
            const int r0 = row0 + warp_m * 64 + i * 16 + gID;
            const int r1 = r0 + 8;
            const float sxa = g_sxinv[r0], sxb = g_sxinv[r1];
            float2 v0, v1;
            v0.x = ((float)acc1[i][j][0] + (float)acc2[i][j][0] * 0.0078125f) * sxa * sw0 + bb.x;
            v0.y = ((float)acc1[i][j][1] + (float)acc2[i][j][1] * 0.0078125f) * sxa * sw1 + bb.y;
            v1.x = ((float)acc1[i][j][2] + (float)acc2[i][j][2] * 0.0078125f) * sxb * sw0 + bb.x;
            v1.y = ((float)acc1[i][j][3] + (float)acc2[i][j][3] * 0.0078125f) * sxb * sw1 + bb.y;
            *reinterpret_cast<float2*>(out + (size_t)r0 * CDIM + col) = v0;
            *reinterpret_cast<float2*>(out + (size_t)r1 * CDIM + col) = v1;
        }
    }
}

// ---------------------------------------------------------------------------
// Launch
// ---------------------------------------------------------------------------
extern "C" void kernel_launch(void* const* d_in, const int* in_sizes, int n_in,
                              void* d_out, int out_size) {
    const float* x  = (const float*)d_in[0];  // [32, 1024, 768]
    const float* Wp = (const float*)d_in[1];  // [768, 768]
    const float* bp = (const float*)d_in[2];  // [768]
    const float* A  = (const float*)d_in[3];  // [4, 16, 768]
    const float* Bw = (const float*)d_in[4];  // [4, 768, 16]
    float* out = (float*)d_out;

    quant_x_kernel<<<TOTAL_ROWS, 192>>>(x);
    quant_w_kernel<<<NUM_MODALS * CDIM, 192>>>(Wp, A, Bw);
    {
        cudaFuncSetAttribute(lora_imma_gemm,
                             cudaFuncAttributeMaxDynamicSharedMemorySize, SMEM_TOTAL);
        dim3 grid(CDIM / 128, TOTAL_ROWS / 128);  // (6, 256)
        lora_imma_gemm<<<grid, 256, SMEM_TOTAL>>>(bp, out);
    }
}

// round 6
// speedup vs baseline: 2.9149x; 2.9149x over previous
#include <cuda_runtime.h>
#include <cuda_fp16.h>
#include <cstdint>

// ---------------------------------------------------------------------------
// Problem constants
// ---------------------------------------------------------------------------
#define NUM_MODALS 4
#define SHARED_IDX 3
#define CDIM       768
#define RANK       16
#define ROWS_PER_M 8192
#define TOTAL_ROWS 32768

// fp16 operand storage (device globals = allowed scratch)
__device__ __half g_Xhi[TOTAL_ROWS * CDIM];
__device__ __half g_Xlo[TOTAL_ROWS * CDIM];
__device__ __half g_Wq[NUM_MODALS * CDIM * CDIM];

// ---------------------------------------------------------------------------
// Helpers
// ---------------------------------------------------------------------------
__device__ __forceinline__ uint32_t smem_u32(const void* p) {
    uint32_t a;
    asm("{ .reg .u64 t; cvta.to.shared.u64 t, %1; cvt.u32.u64 %0, t; }"
        : "=r"(a) : "l"(p));
    return a;
}
__device__ __forceinline__ void cp_async16(uint32_t dst, const void* src) {
    asm volatile("cp.async.cg.shared.global [%0], [%1], 16;"
                 :: "r"(dst), "l"(src) : "memory");
}
__device__ __forceinline__ void cp_commit() {
    asm volatile("cp.async.commit_group;" ::: "memory");
}
template <int N>
__device__ __forceinline__ void cp_wait() {
    asm volatile("cp.async.wait_group %0;" :: "n"(N) : "memory");
}
__device__ __forceinline__ void ldm_x4(uint32_t& r0, uint32_t& r1,
                                       uint32_t& r2, uint32_t& r3,
                                       uint32_t addr) {
    asm volatile("ldmatrix.sync.aligned.m8n8.x4.shared.b16 {%0,%1,%2,%3}, [%4];"
                 : "=r"(r0), "=r"(r1), "=r"(r2), "=r"(r3) : "r"(addr));
}
__device__ __forceinline__ void mma_f16(float& d0, float& d1, float& d2, float& d3,
                                        uint32_t a0, uint32_t a1, uint32_t a2, uint32_t a3,
                                        uint32_t b0, uint32_t b1) {
    asm volatile("mma.sync.aligned.m16n8k16.row.col.f32.f16.f16.f32 "
                 "{%0,%1,%2,%3}, {%4,%5,%6,%7}, {%8,%9}, {%0,%1,%2,%3};"
                 : "+f"(d0), "+f"(d1), "+f"(d2), "+f"(d3)
                 : "r"(a0), "r"(a1), "r"(a2), "r"(a3), "r"(b0), "r"(b1));
}

// ---------------------------------------------------------------------------
// Kernel 1: split x into fp16 hi/lo (float4 vectorized)
// ---------------------------------------------------------------------------
__global__ void split_x_kernel(const float* __restrict__ x) {
    int i = blockIdx.x * blockDim.x + threadIdx.x;   // quad index
    const int nq = TOTAL_ROWS * CDIM / 4;
    if (i >= nq) return;
    float4 v = reinterpret_cast<const float4*>(x)[i];

    __half h0 = __float2half(v.x), h1 = __float2half(v.y);
    __half h2 = __float2half(v.z), h3 = __float2half(v.w);
    __half l0 = __float2half(v.x - __half2float(h0));
    __half l1 = __float2half(v.y - __half2float(h1));
    __half l2 = __float2half(v.z - __half2float(h2));
    __half l3 = __float2half(v.w - __half2float(h3));

    __half2* H = reinterpret_cast<__half2*>(g_Xhi);
    __half2* L = reinterpret_cast<__half2*>(g_Xlo);
    H[i * 2 + 0] = __half2(h0, h1);
    H[i * 2 + 1] = __half2(h2, h3);
    L[i * 2 + 0] = __half2(l0, l1);
    L[i * 2 + 1] = __half2(l2, l3);
}

// ---------------------------------------------------------------------------
// Kernel 2: W_eff = Wp + Bw3*A3 + Bwm*Am, quantize to fp16
// ---------------------------------------------------------------------------
__global__ void weff_kernel(const float* __restrict__ Wp,
                            const float* __restrict__ A,
                            const float* __restrict__ Bw) {
    int idx = blockIdx.x * blockDim.x + threadIdx.x;
    const int total = NUM_MODALS * CDIM * CDIM;
    if (idx >= total) return;
    int c = idx % CDIM;
    int o = (idx / CDIM) % CDIM;
    int m = idx / (CDIM * CDIM);

    const float* A3 = A + SHARED_IDX * RANK * CDIM;
    const float* B3 = Bw + SHARED_IDX * CDIM * RANK;
    const float* Am = A + m * RANK * CDIM;
    const float* Bm = Bw + m * CDIM * RANK;

    float s = Wp[o * CDIM + c];
#pragma unroll
    for (int r = 0; r < RANK; r++) {
        s += B3[o * RANK + r] * A3[r * CDIM + c];
        s += Bm[o * RANK + r] * Am[r * CDIM + c];
    }
    g_Wq[idx] = __float2half(s);
}

// ---------------------------------------------------------------------------
// Kernel 3: fp16 2-term split GEMM via mma.sync.
//   out[row][o] = sum_c x[row][c]*Weff[m][o][c] + bp[o]
// CTA tile 256x128, K-chunk 32 (fp16), 8 warps (2x4), warp tile 128x32.
// 3-stage cp.async pipeline, one __syncthreads per chunk.
// D += Xhi*W + Xlo*W  (single fp32 accumulator set).
// ---------------------------------------------------------------------------
#define BM     256
#define KC2    32                 // fp16 K elems per chunk
#define NCHK   (CDIM / KC2)       // 24
#define LDT    80                 // smem bytes per tile row (64 data + 16 pad)
#define ATB    (BM * LDT)         // 20480 bytes per A operand tile
#define BTB    (128 * LDT)        // 10240 bytes per B operand tile
#define STB    (2 * ATB + BTB)    // 51200 bytes per stage (Xhi,Xlo,W)
#define OFF_AHI 0
#define OFF_ALO ATB
#define OFF_B   (2 * ATB)
#define STAGES 3
#define SMEM_TOTAL (STAGES * STB) // 153600

__device__ __forceinline__ void issue_chunk(const __half* __restrict__ xhi,
                                            const __half* __restrict__ xlo,
                                            const __half* __restrict__ wq,
                                            int row0, int col0, int kbase,
                                            uint32_t sstage, int tid) {
    // A tiles: 256 rows x 64B = 1024 x 16B transfers per tile
#pragma unroll
    for (int i = 0; i < 4; i++) {
        int idx = i * 256 + tid;       // 0..1023
        int row = idx >> 2;            // 0..255
        int ch  = idx & 3;
        uint32_t soff = row * LDT + ch * 16;
        size_t goff = (size_t)(row0 + row) * CDIM + kbase + ch * 8;
        cp_async16(sstage + OFF_AHI + soff, xhi + goff);
        cp_async16(sstage + OFF_ALO + soff, xlo + goff);
    }
    // B tile: 128 rows x 64B = 512 x 16B transfers
#pragma unroll
    for (int i = 0; i < 2; i++) {
        int idx = i * 256 + tid;       // 0..511
        int row = idx >> 2;            // 0..127
        int ch  = idx & 3;
        uint32_t soff = row * LDT + ch * 16;
        size_t goff = (size_t)(col0 + row) * CDIM + kbase + ch * 8;
        cp_async16(sstage + OFF_B + soff, wq + goff);
    }
    cp_commit();
}

__global__ __launch_bounds__(256, 1)
void lora_mma_gemm(const float* __restrict__ bp, float* __restrict__ out) {
    extern __shared__ char smem[];
    const uint32_t sbase = smem_u32(smem);
    const int tid  = threadIdx.x;
    const int wid  = tid >> 5;
    const int lane = tid & 31;
    const int warp_m = wid >> 2;       // 0..1  (128 rows each)
    const int warp_n = wid & 3;        // 0..3  (32 cols each)

    const int row0 = blockIdx.y * BM;
    const int col0 = blockIdx.x * 128;
    const int modality = row0 / ROWS_PER_M;   // BM divides 8192
    const __half* Wq = g_Wq + (size_t)modality * CDIM * CDIM;

    float acc[8][4][4];
#pragma unroll
    for (int i = 0; i < 8; i++)
#pragma unroll
        for (int j = 0; j < 4; j++)
#pragma unroll
            for (int r = 0; r < 4; r++) acc[i][j][r] = 0.f;

    // ldmatrix lane addressing
    const int mat = lane >> 3;         // which 8x8 tile (0..3)
    const int mr  = lane & 7;          // row within tile
    // A frag (16x16): T0=(m0-7,k0-7) T1=(m8-15,k0-7) T2=(m0-7,k8-15) T3=(m8-15,k8-15)
    const int a_row  = warp_m * 128 + (mat & 1) * 8 + mr;    // + i*16
    const int a_colb = (mat >> 1) * 16;                      // bytes, + kk*32
    // B frag (16 cols x 16k): T0=(n0-7,k0-7) T1=(n0-7,k8-15) T2=(n8-15,k0-7) T3=(n8-15,k8-15)
    const int b_row  = warp_n * 32 + (mat >> 1) * 8 + mr;    // + jh*16
    const int b_colb = (mat & 1) * 16;                       // bytes, + kk*32

    // Prologue: 2 chunks in flight
    issue_chunk(g_Xhi, g_Xlo, Wq, row0, col0, 0,   sbase + 0 * STB, tid);
    issue_chunk(g_Xhi, g_Xlo, Wq, row0, col0, KC2, sbase + 1 * STB, tid);

    for (int c = 0; c < NCHK; c++) {
        if (c == NCHK - 1) cp_wait<0>(); else cp_wait<1>();
        __syncthreads();   // also protects buffer (c-1)%3 from the issue below

        if (c + 2 < NCHK)
            issue_chunk(g_Xhi, g_Xlo, Wq, row0, col0, (c + 2) * KC2,
                        sbase + ((c + 2) % STAGES) * STB, tid);

        const uint32_t st = sbase + (c % STAGES) * STB;
        const uint32_t aHi = st + OFF_AHI, aLo = st + OFF_ALO;
        const uint32_t bQ  = st + OFF_B;

#pragma unroll
        for (int kk = 0; kk < 2; kk++) {
            // B fragments (single set, 8 regs as [4][2])
            uint32_t bq[4][2];
#pragma unroll
            for (int jh = 0; jh < 2; jh++) {
                uint32_t boff = (uint32_t)(b_row + jh * 16) * LDT + kk * 32 + b_colb;
                uint32_t r0, r1, r2, r3;
                ldm_x4(r0, r1, r2, r3, bQ + boff);
                bq[2 * jh][0] = r0; bq[2 * jh][1] = r1;
                bq[2 * jh + 1][0] = r2; bq[2 * jh + 1][1] = r3;
            }
            // March down the 8 m-fragments, loading A just-in-time
#pragma unroll
            for (int i = 0; i < 8; i++) {
                uint32_t aoff = (uint32_t)(a_row + i * 16) * LDT + kk * 32 + a_colb;
                uint32_t ah0, ah1, ah2, ah3, al0, al1, al2, al3;
                ldm_x4(ah0, ah1, ah2, ah3, aHi + aoff);
                ldm_x4(al0, al1, al2, al3, aLo + aoff);
#pragma unroll
                for (int j = 0; j < 4; j++) {
                    mma_f16(acc[i][j][0], acc[i][j][1], acc[i][j][2], acc[i][j][3],
                            ah0, ah1, ah2, ah3, bq[j][0], bq[j][1]);
                    mma_f16(acc[i][j][0], acc[i][j][1], acc[i][j][2], acc[i][j][3],
                            al0, al1, al2, al3, bq[j][0], bq[j][1]);
                }
            }
        }
    }
    __syncthreads();

    // Epilogue: bias + store. mma C frag: lane t -> rows (t/4, t/4+8), cols (t%4)*2..+1
    const int gID = lane >> 2;
    const int tg  = lane & 3;
#pragma unroll
    for (int j = 0; j < 4; j++) {
        const int col = col0 + warp_n * 32 + j * 8 + tg * 2;
        const float2 bb = *reinterpret_cast<const float2*>(bp + col);
#pragma unroll
        for (int i = 0; i < 8; i++) {
            const int row = row0 + warp_m * 128 + i * 16 + gID;
            float2 v0 = make_float2(acc[i][j][0] + bb.x, acc[i][j][1] + bb.y);
            float2 v1 = make_float2(acc[i][j][2] + bb.x, acc[i][j][3] + bb.y);
            *reinterpret_cast<float2*>(out + (size_t)row * CDIM + col) = v0;
            *reinterpret_cast<float2*>(out + (size_t)(row + 8) * CDIM + col) = v1;
        }
    }
}

// ---------------------------------------------------------------------------
// Launch
// ---------------------------------------------------------------------------
extern "C" void kernel_launch(void* const* d_in, const int* in_sizes, int n_in,
                              void* d_out, int out_size) {
    const float* x  = (const float*)d_in[0];  // [32, 1024, 768]
    const float* Wp = (const float*)d_in[1];  // [768, 768]
    const float* bp = (const float*)d_in[2];  // [768]
    const float* A  = (const float*)d_in[3];  // [4, 16, 768]
    const float* Bw = (const float*)d_in[4];  // [4, 768, 16]
    float* out = (float*)d_out;

    {
        const int nq = TOTAL_ROWS * CDIM / 4;
        split_x_kernel<<<(nq + 255) / 256, 256>>>(x);
    }
    {
        const int total = NUM_MODALS * CDIM * CDIM;
        weff_kernel<<<(total + 255) / 256, 256>>>(Wp, A, Bw);
    }
    {
        cudaFuncSetAttribute(lora_mma_gemm,
                             cudaFuncAttributeMaxDynamicSharedMemorySize, SMEM_TOTAL);
        dim3 grid(CDIM / 128, TOTAL_ROWS / BM);  // (6, 128)
        lora_mma_gemm<<<grid, 256, SMEM_TOTAL>>>(bp, out);
    }
}

// round 7
// speedup vs baseline: 4.4481x; 1.5260x over previous
#include <cuda_runtime.h>
#include <cuda_fp16.h>
#include <cstdint>

// ---------------------------------------------------------------------------
// Problem constants
// ---------------------------------------------------------------------------
#define NUM_MODALS 4
#define SHARED_IDX 3
#define CDIM       768
#define RANK       16
#define ROWS_PER_M 8192
#define TOTAL_ROWS 32768

// fp16 operand storage (device globals = allowed scratch)
__device__ __half g_Xq[TOTAL_ROWS * CDIM];
__device__ __half g_Wq[NUM_MODALS * CDIM * CDIM];

// ---------------------------------------------------------------------------
// Helpers
// ---------------------------------------------------------------------------
__device__ __forceinline__ uint32_t smem_u32(const void* p) {
    uint32_t a;
    asm("{ .reg .u64 t; cvta.to.shared.u64 t, %1; cvt.u32.u64 %0, t; }"
        : "=r"(a) : "l"(p));
    return a;
}
__device__ __forceinline__ void cp_async16(uint32_t dst, const void* src) {
    asm volatile("cp.async.cg.shared.global [%0], [%1], 16;"
                 :: "r"(dst), "l"(src) : "memory");
}
__device__ __forceinline__ void cp_commit() {
    asm volatile("cp.async.commit_group;" ::: "memory");
}
template <int N>
__device__ __forceinline__ void cp_wait() {
    asm volatile("cp.async.wait_group %0;" :: "n"(N) : "memory");
}
__device__ __forceinline__ void ldm_x4(uint32_t& r0, uint32_t& r1,
                                       uint32_t& r2, uint32_t& r3,
                                       uint32_t addr) {
    asm volatile("ldmatrix.sync.aligned.m8n8.x4.shared.b16 {%0,%1,%2,%3}, [%4];"
                 : "=r"(r0), "=r"(r1), "=r"(r2), "=r"(r3) : "r"(addr));
}
__device__ __forceinline__ void mma_f16(float& d0, float& d1, float& d2, float& d3,
                                        uint32_t a0, uint32_t a1, uint32_t a2, uint32_t a3,
                                        uint32_t b0, uint32_t b1) {
    asm volatile("mma.sync.aligned.m16n8k16.row.col.f32.f16.f16.f32 "
                 "{%0,%1,%2,%3}, {%4,%5,%6,%7}, {%8,%9}, {%0,%1,%2,%3};"
                 : "+f"(d0), "+f"(d1), "+f"(d2), "+f"(d3)
                 : "r"(a0), "r"(a1), "r"(a2), "r"(a3), "r"(b0), "r"(b1));
}

// ---------------------------------------------------------------------------
// Kernel 1: convert x to fp16 (float4 vectorized)
// ---------------------------------------------------------------------------
__global__ void cvt_x_kernel(const float* __restrict__ x) {
    int i = blockIdx.x * blockDim.x + threadIdx.x;   // quad index
    const int nq = TOTAL_ROWS * CDIM / 4;
    if (i >= nq) return;
    float4 v = reinterpret_cast<const float4*>(x)[i];
    __half2* H = reinterpret_cast<__half2*>(g_Xq);
    H[i * 2 + 0] = __half2(__float2half(v.x), __float2half(v.y));
    H[i * 2 + 1] = __half2(__float2half(v.z), __float2half(v.w));
}

// ---------------------------------------------------------------------------
// Kernel 2: W_eff = Wp + Bw3*A3 + Bwm*Am, quantize to fp16
// ---------------------------------------------------------------------------
__global__ void weff_kernel(const float* __restrict__ Wp,
                            const float* __restrict__ A,
                            const float* __restrict__ Bw) {
    int idx = blockIdx.x * blockDim.x + threadIdx.x;
    const int total = NUM_MODALS * CDIM * CDIM;
    if (idx >= total) return;
    int c = idx % CDIM;
    int o = (idx / CDIM) % CDIM;
    int m = idx / (CDIM * CDIM);

    const float* A3 = A + SHARED_IDX * RANK * CDIM;
    const float* B3 = Bw + SHARED_IDX * CDIM * RANK;
    const float* Am = A + m * RANK * CDIM;
    const float* Bm = Bw + m * CDIM * RANK;

    float s = Wp[o * CDIM + c];
#pragma unroll
    for (int r = 0; r < RANK; r++) {
        s += B3[o * RANK + r] * A3[r * CDIM + c];
        s += Bm[o * RANK + r] * Am[r * CDIM + c];
    }
    g_Wq[idx] = __float2half(s);
}

// ---------------------------------------------------------------------------
// Kernel 3: fp16 GEMM via mma.sync (single term, fp32 accumulate).
//   out[row][o] = sum_c x[row][c]*Weff[m][o][c] + bp[o]
// CTA tile 256x128, K-chunk 32 (fp16), 8 warps (2x4), warp tile 128x32.
// 4-stage cp.async pipeline, one __syncthreads per chunk.
// ---------------------------------------------------------------------------
#define BM     256
#define KC2    32                 // fp16 K elems per chunk
#define NCHK   (CDIM / KC2)       // 24
#define LDT    80                 // smem bytes per tile row (64 data + 16 pad)
#define ATB    (BM * LDT)         // 20480 bytes (A tile)
#define BTB    (128 * LDT)        // 10240 bytes (B tile)
#define STB    (ATB + BTB)        // 30720 bytes per stage
#define OFF_A  0
#define OFF_B  ATB
#define STAGES 4
#define SMEM_TOTAL (STAGES * STB) // 122880

__device__ __forceinline__ void issue_chunk(const __half* __restrict__ xq,
                                            const __half* __restrict__ wq,
                                            int row0, int col0, int kbase,
                                            uint32_t sstage, int tid) {
    // A tile: 256 rows x 64B = 1024 x 16B transfers
#pragma unroll
    for (int i = 0; i < 4; i++) {
        int idx = i * 256 + tid;       // 0..1023
        int row = idx >> 2;            // 0..255
        int ch  = idx & 3;
        uint32_t soff = row * LDT + ch * 16;
        size_t goff = (size_t)(row0 + row) * CDIM + kbase + ch * 8;
        cp_async16(sstage + OFF_A + soff, xq + goff);
    }
    // B tile: 128 rows x 64B = 512 x 16B transfers
#pragma unroll
    for (int i = 0; i < 2; i++) {
        int idx = i * 256 + tid;       // 0..511
        int row = idx >> 2;            // 0..127
        int ch  = idx & 3;
        uint32_t soff = row * LDT + ch * 16;
        size_t goff = (size_t)(col0 + row) * CDIM + kbase + ch * 8;
        cp_async16(sstage + OFF_B + soff, wq + goff);
    }
    cp_commit();
}

__global__ __launch_bounds__(256, 1)
void lora_mma_gemm(const float* __restrict__ bp, float* __restrict__ out) {
    extern __shared__ char smem[];
    const uint32_t sbase = smem_u32(smem);
    const int tid  = threadIdx.x;
    const int wid  = tid >> 5;
    const int lane = tid & 31;
    const int warp_m = wid >> 2;       // 0..1  (128 rows each)
    const int warp_n = wid & 3;        // 0..3  (32 cols each)

    const int row0 = blockIdx.y * BM;
    const int col0 = blockIdx.x * 128;
    const int modality = row0 / ROWS_PER_M;   // BM divides 8192
    const __half* Wq = g_Wq + (size_t)modality * CDIM * CDIM;

    float acc[8][4][4];
#pragma unroll
    for (int i = 0; i < 8; i++)
#pragma unroll
        for (int j = 0; j < 4; j++)
#pragma unroll
            for (int r = 0; r < 4; r++) acc[i][j][r] = 0.f;

    // ldmatrix lane addressing
    const int mat = lane >> 3;         // which 8x8 tile (0..3)
    const int mr  = lane & 7;          // row within tile
    const int a_row  = warp_m * 128 + (mat & 1) * 8 + mr;    // + i*16
    const int a_colb = (mat >> 1) * 16;                      // bytes, + kk*32
    const int b_row  = warp_n * 32 + (mat >> 1) * 8 + mr;    // + jh*16
    const int b_colb = (mat & 1) * 16;                       // bytes, + kk*32

    // Prologue: 3 chunks in flight
    issue_chunk(g_Xq, Wq, row0, col0, 0,       sbase + 0 * STB, tid);
    issue_chunk(g_Xq, Wq, row0, col0, KC2,     sbase + 1 * STB, tid);
    issue_chunk(g_Xq, Wq, row0, col0, 2 * KC2, sbase + 2 * STB, tid);

    for (int c = 0; c < NCHK; c++) {
        // ensure chunk c has landed: pending-after-wait = #issued-beyond-c
        if (c + 1 >= NCHK)      cp_wait<0>();
        else if (c + 2 >= NCHK) cp_wait<1>();
        else                    cp_wait<2>();
        __syncthreads();   // also protects slot (c-1)%4 from the issue below

        if (c + 3 < NCHK)
            issue_chunk(g_Xq, Wq, row0, col0, (c + 3) * KC2,
                        sbase + ((c + 3) % STAGES) * STB, tid);

        const uint32_t st = sbase + (c % STAGES) * STB;
        const uint32_t sA = st + OFF_A, sB = st + OFF_B;

#pragma unroll
        for (int kk = 0; kk < 2; kk++) {
            uint32_t bq[4][2];
#pragma unroll
            for (int jh = 0; jh < 2; jh++) {
                uint32_t boff = (uint32_t)(b_row + jh * 16) * LDT + kk * 32 + b_colb;
                uint32_t r0, r1, r2, r3;
                ldm_x4(r0, r1, r2, r3, sB + boff);
                bq[2 * jh][0] = r0; bq[2 * jh][1] = r1;
                bq[2 * jh + 1][0] = r2; bq[2 * jh + 1][1] = r3;
            }
#pragma unroll
            for (int i = 0; i < 8; i++) {
                uint32_t aoff = (uint32_t)(a_row + i * 16) * LDT + kk * 32 + a_colb;
                uint32_t a0, a1, a2, a3;
                ldm_x4(a0, a1, a2, a3, sA + aoff);
#pragma unroll
                for (int j = 0; j < 4; j++)
                    mma_f16(acc[i][j][0], acc[i][j][1], acc[i][j][2], acc[i][j][3],
                            a0, a1, a2, a3, bq[j][0], bq[j][1]);
            }
        }
    }
    __syncthreads();

    // Epilogue: bias + store. mma C frag: lane t -> rows (t/4, t/4+8), cols (t%4)*2..+1
    const int gID = lane >> 2;
    const int tg  = lane & 3;
#pragma unroll
    for (int j = 0; j < 4; j++) {
        const int col = col0 + warp_n * 32 + j * 8 + tg * 2;
        const float2 bb = *reinterpret_cast<const float2*>(bp + col);
#pragma unroll
        for (int i = 0; i < 8; i++) {
            const int row = row0 + warp_m * 128 + i * 16 + gID;
            float2 v0 = make_float2(acc[i][j][0] + bb.x, acc[i][j][1] + bb.y);
            float2 v1 = make_float2(acc[i][j][2] + bb.x, acc[i][j][3] + bb.y);
            *reinterpret_cast<float2*>(out + (size_t)row * CDIM + col) = v0;
            *reinterpret_cast<float2*>(out + (size_t)(row + 8) * CDIM + col) = v1;
        }
    }
}

// ---------------------------------------------------------------------------
// Launch
// ---------------------------------------------------------------------------
extern "C" void kernel_launch(void* const* d_in, const int* in_sizes, int n_in,
                              void* d_out, int out_size) {
    const float* x  = (const float*)d_in[0];  // [32, 1024, 768]
    const float* Wp = (const float*)d_in[1];  // [768, 768]
    const float* bp = (const float*)d_in[2];  // [768]
    const float* A  = (const float*)d_in[3];  // [4, 16, 768]
    const float* Bw = (const float*)d_in[4];  // [4, 768, 16]
    float* out = (float*)d_out;

    {
        const int nq = TOTAL_ROWS * CDIM / 4;
        cvt_x_kernel<<<(nq + 255) / 256, 256>>>(x);
    }
    {
        const int total = NUM_MODALS * CDIM * CDIM;
        weff_kernel<<<(total + 255) / 256, 256>>>(Wp, A, Bw);
    }
    {
        cudaFuncSetAttribute(lora_mma_gemm,
                             cudaFuncAttributeMaxDynamicSharedMemorySize, SMEM_TOTAL);
        dim3 grid(CDIM / 128, TOTAL_ROWS / BM);  // (6, 128)
        lora_mma_gemm<<<grid, 256, SMEM_TOTAL>>>(bp, out);
    }
}

// round 8
// speedup vs baseline: 5.6987x; 1.2811x over previous
#include <cuda_runtime.h>
#include <cuda_fp16.h>
#include <cstdint>

// ---------------------------------------------------------------------------
// Problem constants
// ---------------------------------------------------------------------------
#define NUM_MODALS 4
#define SHARED_IDX 3
#define CDIM       768
#define RANK       16
#define ROWS_PER_M 8192
#define TOTAL_ROWS 32768

// fp16 operand storage (device globals = allowed scratch)
__device__ __half g_Xq[TOTAL_ROWS * CDIM];
__device__ __half g_Wq[NUM_MODALS * CDIM * CDIM];

// ---------------------------------------------------------------------------
// Helpers
// ---------------------------------------------------------------------------
__device__ __forceinline__ uint32_t smem_u32(const void* p) {
    uint32_t a;
    asm("{ .reg .u64 t; cvta.to.shared.u64 t, %1; cvt.u32.u64 %0, t; }"
        : "=r"(a) : "l"(p));
    return a;
}
__device__ __forceinline__ void cp_async16(uint32_t dst, const void* src) {
    asm volatile("cp.async.cg.shared.global [%0], [%1], 16;"
                 :: "r"(dst), "l"(src) : "memory");
}
__device__ __forceinline__ void cp_commit() {
    asm volatile("cp.async.commit_group;" ::: "memory");
}
template <int N>
__device__ __forceinline__ void cp_wait() {
    asm volatile("cp.async.wait_group %0;" :: "n"(N) : "memory");
}
__device__ __forceinline__ void ldm_x4(uint32_t& r0, uint32_t& r1,
                                       uint32_t& r2, uint32_t& r3,
                                       uint32_t addr) {
    asm volatile("ldmatrix.sync.aligned.m8n8.x4.shared.b16 {%0,%1,%2,%3}, [%4];"
                 : "=r"(r0), "=r"(r1), "=r"(r2), "=r"(r3) : "r"(addr));
}
__device__ __forceinline__ void mma_f16(float& d0, float& d1, float& d2, float& d3,
                                        uint32_t a0, uint32_t a1, uint32_t a2, uint32_t a3,
                                        uint32_t b0, uint32_t b1) {
    asm volatile("mma.sync.aligned.m16n8k16.row.col.f32.f16.f16.f32 "
                 "{%0,%1,%2,%3}, {%4,%5,%6,%7}, {%8,%9}, {%0,%1,%2,%3};"
                 : "+f"(d0), "+f"(d1), "+f"(d2), "+f"(d3)
                 : "r"(a0), "r"(a1), "r"(a2), "r"(a3), "r"(b0), "r"(b1));
}

// ---------------------------------------------------------------------------
// Kernel 1: fused prep.
//   blocks [0, XBLK)      : convert x -> fp16 (float4 vectorized)
//   blocks [XBLK, TOTALB) : W_eff = Wp + Bw3*A3 + Bwm*Am -> fp16
// ---------------------------------------------------------------------------
#define XQUADS (TOTAL_ROWS * CDIM / 4)            // 6291456
#define XBLK   (XQUADS / 256)                     // 24576
#define WELEMS (NUM_MODALS * CDIM * CDIM)         // 2359296
#define WBLK   (WELEMS / 256)                     // 9216
#define TOTALB (XBLK + WBLK)                      // 33792

__global__ __launch_bounds__(256)
void prep_kernel(const float* __restrict__ x,
                 const float* __restrict__ Wp,
                 const float* __restrict__ A,
                 const float* __restrict__ Bw) {
    const int b = blockIdx.x;
    if (b < XBLK) {
        const int i = b * 256 + threadIdx.x;       // quad index
        float4 v = reinterpret_cast<const float4*>(x)[i];
        __half2* H = reinterpret_cast<__half2*>(g_Xq);
        H[i * 2 + 0] = __half2(__float2half(v.x), __float2half(v.y));
        H[i * 2 + 1] = __half2(__float2half(v.z), __float2half(v.w));
    } else {
        const int idx = (b - XBLK) * 256 + threadIdx.x;
        const int c = idx % CDIM;
        const int o = (idx / CDIM) % CDIM;
        const int m = idx / (CDIM * CDIM);

        const float* A3 = A + SHARED_IDX * RANK * CDIM;
        const float* B3 = Bw + SHARED_IDX * CDIM * RANK;
        const float* Am = A + m * RANK * CDIM;
        const float* Bm = Bw + m * CDIM * RANK;

        float s = Wp[o * CDIM + c];
#pragma unroll
        for (int r = 0; r < RANK; r++) {
            s += B3[o * RANK + r] * A3[r * CDIM + c];
            s += Bm[o * RANK + r] * Am[r * CDIM + c];
        }
        g_Wq[idx] = __float2half(s);
    }
}

// ---------------------------------------------------------------------------
// Kernel 2: fp16 GEMM via mma.sync (fp32 accumulate).
//   out[row][o] = sum_c x[row][c]*Weff[m][o][c] + bp[o]
// CTA tile 128x128, 128 threads (4 warps, 2x2), warp tile 64x64.
// K-chunk 32, 4-stage cp.async pipeline, 2 CTAs/SM co-resident.
// ---------------------------------------------------------------------------
#define BM     128
#define KC2    32                 // fp16 K elems per chunk
#define NCHK   (CDIM / KC2)       // 24
#define LDT    80                 // smem bytes per tile row (64 data + 16 pad)
#define ATB    (BM * LDT)         // 10240 bytes (A tile)
#define BTB    (128 * LDT)        // 10240 bytes (B tile)
#define STB    (ATB + BTB)        // 20480 bytes per stage
#define OFF_A  0
#define OFF_B  ATB
#define STAGES 4
#define SMEM_TOTAL (STAGES * STB) // 81920  -> 2 CTAs/SM

__device__ __forceinline__ void issue_chunk(const __half* __restrict__ xq,
                                            const __half* __restrict__ wq,
                                            int row0, int col0, int kbase,
                                            uint32_t sstage, int tid) {
    // A tile: 128 rows x 64B = 512 x 16B transfers
#pragma unroll
    for (int i = 0; i < 4; i++) {
        int idx = i * 128 + tid;       // 0..511
        int row = idx >> 2;            // 0..127
        int ch  = idx & 3;
        uint32_t soff = row * LDT + ch * 16;
        size_t goff = (size_t)(row0 + row) * CDIM + kbase + ch * 8;
        cp_async16(sstage + OFF_A + soff, xq + goff);
    }
    // B tile: 128 rows x 64B = 512 x 16B transfers
#pragma unroll
    for (int i = 0; i < 4; i++) {
        int idx = i * 128 + tid;
        int row = idx >> 2;
        int ch  = idx & 3;
        uint32_t soff = row * LDT + ch * 16;
        size_t goff = (size_t)(col0 + row) * CDIM + kbase + ch * 8;
        cp_async16(sstage + OFF_B + soff, wq + goff);
    }
    cp_commit();
}

__global__ __launch_bounds__(128, 2)
void lora_mma_gemm(const float* __restrict__ bp, float* __restrict__ out) {
    extern __shared__ char smem[];
    const uint32_t sbase = smem_u32(smem);
    const int tid  = threadIdx.x;
    const int wid  = tid >> 5;
    const int lane = tid & 31;
    const int warp_m = wid >> 1;       // 0..1  (64 rows each)
    const int warp_n = wid & 1;        // 0..1  (64 cols each)

    const int row0 = blockIdx.y * BM;
    const int col0 = blockIdx.x * 128;
    const int modality = row0 / ROWS_PER_M;
    const __half* Wq = g_Wq + (size_t)modality * CDIM * CDIM;

    float acc[4][8][4];
#pragma unroll
    for (int i = 0; i < 4; i++)
#pragma unroll
        for (int j = 0; j < 8; j++)
#pragma unroll
            for (int r = 0; r < 4; r++) acc[i][j][r] = 0.f;

    // ldmatrix lane addressing
    const int mat = lane >> 3;         // which 8x8 tile (0..3)
    const int mr  = lane & 7;          // row within tile
    const int a_row  = warp_m * 64 + (mat & 1) * 8 + mr;     // + i*16
    const int a_colb = (mat >> 1) * 16;                      // bytes, + kk*32
    const int b_row  = warp_n * 64 + (mat >> 1) * 8 + mr;    // + jh*16
    const int b_colb = (mat & 1) * 16;                       // bytes, + kk*32

    // Prologue: 3 chunks in flight
    issue_chunk(g_Xq, Wq, row0, col0, 0,       sbase + 0 * STB, tid);
    issue_chunk(g_Xq, Wq, row0, col0, KC2,     sbase + 1 * STB, tid);
    issue_chunk(g_Xq, Wq, row0, col0, 2 * KC2, sbase + 2 * STB, tid);

    for (int c = 0; c < NCHK; c++) {
        if (c + 1 >= NCHK)      cp_wait<0>();
        else if (c + 2 >= NCHK) cp_wait<1>();
        else                    cp_wait<2>();
        __syncthreads();   // also protects slot (c-1)%4 from the issue below

        if (c + 3 < NCHK)
            issue_chunk(g_Xq, Wq, row0, col0, (c + 3) * KC2,
                        sbase + ((c + 3) % STAGES) * STB, tid);

        const uint32_t st = sbase + (c % STAGES) * STB;
        const uint32_t sA = st + OFF_A, sB = st + OFF_B;

#pragma unroll
        for (int kk = 0; kk < 2; kk++) {
            uint32_t bq[8][2];
#pragma unroll
            for (int jh = 0; jh < 4; jh++) {   // 4 x 16-col fragments
                uint32_t boff = (uint32_t)(b_row + jh * 16) * LDT + kk * 32 + b_colb;
                uint32_t r0, r1, r2, r3;
                ldm_x4(r0, r1, r2, r3, sB + boff);
                bq[2 * jh][0] = r0; bq[2 * jh][1] = r1;
                bq[2 * jh + 1][0] = r2; bq[2 * jh + 1][1] = r3;
            }
#pragma unroll
            for (int i = 0; i < 4; i++) {
                uint32_t aoff = (uint32_t)(a_row + i * 16) * LDT + kk * 32 + a_colb;
                uint32_t a0, a1, a2, a3;
                ldm_x4(a0, a1, a2, a3, sA + aoff);
#pragma unroll
                for (int j = 0; j < 8; j++)
                    mma_f16(acc[i][j][0], acc[i][j][1], acc[i][j][2], acc[i][j][3],
                            a0, a1, a2, a3, bq[j][0], bq[j][1]);
            }
        }
    }
    __syncthreads();

    // Epilogue: bias + store. mma C frag: lane t -> rows (t/4, t/4+8), cols (t%4)*2..+1
    const int gID = lane >> 2;
    const int tg  = lane & 3;
#pragma unroll
    for (int j = 0; j < 8; j++) {
        const int col = col0 + warp_n * 64 + j * 8 + tg * 2;
        const float2 bb = *reinterpret_cast<const float2*>(bp + col);
#pragma unroll
        for (int i = 0; i < 4; i++) {
            const int row = row0 + warp_m * 64 + i * 16 + gID;
            float2 v0 = make_float2(acc[i][j][0] + bb.x, acc[i][j][1] + bb.y);
            float2 v1 = make_float2(acc[i][j][2] + bb.x, acc[i][j][3] + bb.y);
            *reinterpret_cast<float2*>(out + (size_t)row * CDIM + col) = v0;
            *reinterpret_cast<float2*>(out + (size_t)(row + 8) * CDIM + col) = v1;
        }
    }
}

// ---------------------------------------------------------------------------
// Launch
// ---------------------------------------------------------------------------
extern "C" void kernel_launch(void* const* d_in, const int* in_sizes, int n_in,
                              void* d_out, int out_size) {
    const float* x  = (const float*)d_in[0];  // [32, 1024, 768]
    const float* Wp = (const float*)d_in[1];  // [768, 768]
    const float* bp = (const float*)d_in[2];  // [768]
    const float* A  = (const float*)d_in[3];  // [4, 16, 768]
    const float* Bw = (const float*)d_in[4];  // [4, 768, 16]
    float* out = (float*)d_out;

    prep_kernel<<<TOTALB, 256>>>(x, Wp, A, Bw);
    {
        cudaFuncSetAttribute(lora_mma_gemm,
                             cudaFuncAttributeMaxDynamicSharedMemorySize, SMEM_TOTAL);
        dim3 grid(CDIM / 128, TOTAL_ROWS / BM);  // (6, 256)
        lora_mma_gemm<<<grid, 128, SMEM_TOTAL>>>(bp, out);
    }
}